// round 16
// baseline (speedup 1.0000x reference)
#include <cuda_runtime.h>
#include <math.h>
#include <cstdint>

#define FULL_MASK 0xFFFFFFFFu
typedef unsigned long long ull;

__device__ __forceinline__ ull pk2(float lo, float hi) {
    ull r; asm("mov.b64 %0, {%1, %2};" : "=l"(r) : "f"(lo), "f"(hi)); return r;
}
__device__ __forceinline__ void fma2(ull& d, ull a, ull b) {
    asm("fma.rn.f32x2 %0, %1, %2, %0;" : "+l"(d) : "l"(a), "l"(b));
}
__device__ __forceinline__ void unpk(ull v, float& a, float& b) {
    asm("mov.b64 {%0, %1}, %2;" : "=f"(a), "=f"(b) : "l"(v));
}
__device__ __forceinline__ void mbar_wait(uint32_t mbar, int parity) {
    asm volatile(
        "{\n\t.reg .pred P;\n\t"
        "WAIT_%=:\n\t"
        "mbarrier.try_wait.parity.acquire.cta.shared::cta.b64 P, [%0], %1, 0x989680;\n\t"
        "@P bra.uni DONE_%=;\n\t"
        "bra.uni WAIT_%=;\n\t"
        "DONE_%=:\n\t}"
        :: "r"(mbar), "r"(parity) : "memory");
}

// bs=65536, S=10, D=100, H=16, 5 greedy steps.
// 4 batches per warp; lane = (b4 = lane>>3, g = (lane>>2)&1, hq = lane&3).
// Lane owns a 5-row x 4-col tile: rows 5g..5g+4, cols h0..h0+3 (h0 = 4*hq).
// R15 = R14 (cp.async.bulk corpus staging, best: 155.6us) with src/score PACKED
// into the s_ic padding columns (16..19) -> block smem 58880 -> 57664 B, which
// lifts residency 3 -> 4 blocks/SM (9 -> 12 warps) to cover the per-step serial
// latency chain that R14 exposed (occ 11.6%, issue 37.5%, L1 only 64.8%).
//
// FROZEN numerics contract (rel_err 9.309e-8 since R4):
//   - every dot: single-accumulator sequential fmaf chain (ascending index), bias AFTER
//   - f32x2 pairs two INDEPENDENT h-chains (lo/hi rounded separately)
//   - score: ONE lane per (batch,row), h=0..15 ascending scalar chain
//   - src = mean(ui): append-order sum; /2,/4 exact mul; /3,/5 via __fdiv_rn
//   - softmax skipped (monotone); first-index argmax via strict >
#define S_IC(b4, r)  (s_icA + ((w * 4 + (b4)) * 10 + (r)) * 20)
// src[b4][4i..4i+3]  lives at S_IC(b4, i)[16..19],  i = 0..3
// score[b4][j]       lives at S_IC(b4, 4 + (j>>1))[16 + (j&1)], j = 0..9

__global__ __launch_bounds__(96, 4)
void attn_greedy_kernel(const float* __restrict__ g_ui,     // [bs,16]
                        const float* __restrict__ g_corp,   // [bs,10,100]
                        const float* __restrict__ g_wp,     // [100,16]
                        const float* __restrict__ g_bp,     // [16]
                        const float* __restrict__ g_wk,     // [16,16]
                        const float* __restrict__ g_bk,     // [16]
                        float* __restrict__ g_out,          // [bs,6,16]
                        int n_batch)
{
    extern __shared__ __align__(16) char smem_raw[];
    float* s_corpA = (float*)smem_raw;                    // [3][4000] corpus tiles
    float* s_icA   = (float*)(smem_raw + 48000);          // [3][4][10][20] (+ packed src/score)
    ull*   s_mbarA = (ull*)(smem_raw + 57600);            // [3] mbarriers

    const int tid  = threadIdx.x;
    const int w    = tid >> 5;
    const int lane = tid & 31;
    const int b4   = lane >> 3;
    const int g    = (lane >> 2) & 1;
    const int hq   = lane & 3;
    const int h0   = hq << 2;

    float* scorp = s_corpA + w * 4000;
    const uint32_t mb = (uint32_t)__cvta_generic_to_shared(&s_mbarA[w]);
    if (lane == 0)
        asm volatile("mbarrier.init.shared.b64 [%0], %1;" :: "r"(mb), "r"(1) : "memory");
    __syncwarp();

    const int warp_id = blockIdx.x * 3 + w;
    const int n_warps = gridDim.x * 3;
    const int n_quad  = (n_batch + 3) >> 2;

    const float4 bp4 = __ldg((const float4*)(g_bp + h0));
    const float4 bk4 = __ldg((const float4*)(g_bk + h0));

    // ---- issue first corpus bulk (lane 0) ----
    int ph = 0;
    if (warp_id < n_quad && lane == 0) {
        asm volatile("mbarrier.arrive.expect_tx.shared.b64 _, [%0], %1;"
                     :: "r"(mb), "r"(16000) : "memory");
        #pragma unroll
        for (int jb = 0; jb < 4; jb++) {
            int bj = (warp_id << 2) + jb; if (bj >= n_batch) bj = n_batch - 1;
            uint32_t dst = (uint32_t)__cvta_generic_to_shared(scorp + jb * 1000);
            asm volatile("cp.async.bulk.shared::cta.global.mbarrier::complete_tx::bytes "
                         "[%0], [%1], %2, [%3];"
                         :: "r"(dst), "l"(g_corp + (size_t)bj * 1000), "r"(4000), "r"(mb)
                         : "memory");
        }
    }

    for (int qd = warp_id; qd < n_quad; qd += n_warps) {
        const int  b     = (qd << 2) + b4;
        const bool valid = (b < n_batch);
        const int  bl    = valid ? b : (n_batch - 1);

        // ---- ui (independent of corpus; overlaps the bulk) ----
        float4 uiv = __ldg((const float4*)(g_ui + (size_t)bl * 16 + h0));
        float sum0 = uiv.x, sum1 = uiv.y, sum2 = uiv.z, sum3 = uiv.w;
        if (g == 0) {
            *(float4*)&S_IC(b4, hq)[16] = uiv;                 // src slice (pad cols)
            if (valid) *(float4*)(g_out + (size_t)b * 96 + h0) = uiv;
        }

        // ---- wait for this quad's corpus tile ----
        mbar_wait(mb, ph); ph ^= 1;

        // ---- projection: ic0[row][h] = seq-fma_{d=0..99} corp[row,d]*Wp[d,h], +bp ----
        ull acc[5][2];
        #pragma unroll
        for (int j = 0; j < 5; j++) { acc[j][0] = 0ull; acc[j][1] = 0ull; }
        const float* crow = scorp + b4 * 1000 + (5 * g) * 100;   // conflict-free LDS.128
        #pragma unroll 5
        for (int c = 0; c < 25; c++) {
            float4 x[5];
            #pragma unroll
            for (int j = 0; j < 5; j++)
                x[j] = *(const float4*)(crow + j * 100 + 4 * c);
            #pragma unroll
            for (int q = 0; q < 4; q++) {                        // d ascending
                ulonglong2 wp2 = __ldg((const ulonglong2*)(g_wp + (4*c + q) * 16 + h0));
                #pragma unroll
                for (int j = 0; j < 5; j++) {
                    float cd = (q == 0) ? x[j].x : (q == 1) ? x[j].y : (q == 2) ? x[j].z : x[j].w;
                    ull cdd = pk2(cd, cd);
                    fma2(acc[j][0], cdd, wp2.x);    // chains h0, h0+1
                    fma2(acc[j][1], cdd, wp2.y);    // chains h0+2, h0+3
                }
            }
        }
        #pragma unroll
        for (int j = 0; j < 5; j++) {
            float a0, a1, a2, a3;
            unpk(acc[j][0], a0, a1); unpk(acc[j][1], a2, a3);
            *(float4*)&S_IC(b4, 5*g + j)[h0] =
                make_float4(a0 + bp4.x, a1 + bp4.y, a2 + bp4.z, a3 + bp4.w);
        }
        __syncwarp();                       // all lanes done reading scorp

        // ---- issue NEXT quad's corpus bulk (lands under the step-loop) ----
        {
            const int nqd = qd + n_warps;
            if (lane == 0 && nqd < n_quad) {
                asm volatile("mbarrier.arrive.expect_tx.shared.b64 _, [%0], %1;"
                             :: "r"(mb), "r"(16000) : "memory");
                #pragma unroll
                for (int jb = 0; jb < 4; jb++) {
                    int bj = (nqd << 2) + jb; if (bj >= n_batch) bj = n_batch - 1;
                    uint32_t dst = (uint32_t)__cvta_generic_to_shared(scorp + jb * 1000);
                    asm volatile("cp.async.bulk.shared::cta.global.mbarrier::complete_tx::bytes "
                                 "[%0], [%1], %2, [%3];"
                                 :: "r"(dst), "l"(g_corp + (size_t)bj * 1000), "r"(4000), "r"(mb)
                                 : "memory");
                }
            }
        }

        // ---- 5 greedy steps ----
        for (int t = 1; t <= 5; t++) {
            // nic[row][h] = seq-fma_{k=0..15} ic[row][k]*Wk[k][h], +bk
            ull np[5][2];
            #pragma unroll
            for (int j = 0; j < 5; j++) { np[j][0] = 0ull; np[j][1] = 0ull; }
            #pragma unroll
            for (int kc = 0; kc < 4; kc++) {
                float4 iv[5];
                #pragma unroll
                for (int j = 0; j < 5; j++)
                    iv[j] = *(const float4*)&S_IC(b4, 5*g + j)[4 * kc];
                #pragma unroll
                for (int q = 0; q < 4; q++) {                    // k = 4kc+q ascending
                    ulonglong2 wk2 = __ldg((const ulonglong2*)(g_wk + (4*kc + q) * 16 + h0));
                    #pragma unroll
                    for (int j = 0; j < 5; j++) {
                        float cd = (q == 0) ? iv[j].x : (q == 1) ? iv[j].y
                                 : (q == 2) ? iv[j].z : iv[j].w;
                        ull iv2 = pk2(cd, cd);
                        fma2(np[j][0], iv2, wk2.x);
                        fma2(np[j][1], iv2, wk2.y);
                    }
                }
            }
            float nic[5][4];
            #pragma unroll
            for (int j = 0; j < 5; j++) {
                float a0, a1, a2, a3;
                unpk(np[j][0], a0, a1); unpk(np[j][1], a2, a3);
                nic[j][0] = a0 + bk4.x; nic[j][1] = a1 + bk4.y;
                nic[j][2] = a2 + bk4.z; nic[j][3] = a3 + bk4.w;
            }
            __syncwarp();                   // all k-reads of old ic done
            #pragma unroll
            for (int j = 0; j < 5; j++)
                *(float4*)&S_IC(b4, 5*g + j)[h0] =
                    make_float4(nic[j][0], nic[j][1], nic[j][2], nic[j][3]);
            __syncwarp();                   // new ic visible

            // score[(sb,row)] = seq-fma_{h=0..15} ic[row][h]*src[h]  (one lane per row)
            {
                const int sb = lane >> 3, sr = lane & 7;
                const float* icr = S_IC(sb, sr);
                float a = 0.f;
                #pragma unroll
                for (int i = 0; i < 4; i++) {
                    float4 xx = *(const float4*)(icr + 4*i);
                    float4 yy = *(const float4*)&S_IC(sb, i)[16];         // src slice
                    a = fmaf(xx.x, yy.x, a); a = fmaf(xx.y, yy.y, a);     // h ascending
                    a = fmaf(xx.z, yy.z, a); a = fmaf(xx.w, yy.w, a);
                }
                S_IC(sb, 4 + (sr >> 1))[16 + (sr & 1)] = a;               // score[sr]
                if (sr < 2) {               // rows 8,9
                    const float* icr2 = S_IC(sb, 8 + sr);
                    float a2 = 0.f;
                    #pragma unroll
                    for (int i = 0; i < 4; i++) {
                        float4 xx = *(const float4*)(icr2 + 4*i);
                        float4 yy = *(const float4*)&S_IC(sb, i)[16];
                        a2 = fmaf(xx.x, yy.x, a2); a2 = fmaf(xx.y, yy.y, a2);
                        a2 = fmaf(xx.z, yy.z, a2); a2 = fmaf(xx.w, yy.w, a2);
                    }
                    S_IC(sb, 8)[16 + (sr & 1)] = a2;                      // score[8+sr]
                }
            }
            __syncwarp();

            // first-index argmax (strict >, ascending row)
            float bv = -INFINITY; int idx = 0;
            #pragma unroll
            for (int j = 0; j < 10; j++) {
                float v = S_IC(b4, 4 + (j >> 1))[16 + (j & 1)];           // broadcast LDS
                if (v > bv) { bv = v; idx = j; }
            }

            // gather selected row via register select + shfl
            const int jj = idx - 5 * g;     // 0..4 if this g owns the row
            float c0 = nic[0][0], c1 = nic[0][1], c2 = nic[0][2], c3 = nic[0][3];
            #pragma unroll
            for (int j = 1; j < 5; j++)
                if (jj == j) { c0 = nic[j][0]; c1 = nic[j][1]; c2 = nic[j][2]; c3 = nic[j][3]; }
            const int srcl = (lane & 24) | ((idx >= 5) ? 4 : 0) | hq;
            float it0 = __shfl_sync(FULL_MASK, c0, srcl);
            float it1 = __shfl_sync(FULL_MASK, c1, srcl);
            float it2 = __shfl_sync(FULL_MASK, c2, srcl);
            float it3 = __shfl_sync(FULL_MASK, c3, srcl);

            sum0 += it0; sum1 += it1; sum2 += it2; sum3 += it3;           // append order
            if (g == 0) {
                if (valid)
                    *(float4*)(g_out + (size_t)b * 96 + (size_t)t * 16 + h0) =
                        make_float4(it0, it1, it2, it3);
                if (t < 5) {
                    float s0, s1, s2, s3;
                    if (t == 1)      { s0 = sum0*0.5f;  s1 = sum1*0.5f;  s2 = sum2*0.5f;  s3 = sum3*0.5f;  }
                    else if (t == 3) { s0 = sum0*0.25f; s1 = sum1*0.25f; s2 = sum2*0.25f; s3 = sum3*0.25f; }
                    else {
                        const float dv = (float)(t + 1);
                        s0 = __fdiv_rn(sum0, dv); s1 = __fdiv_rn(sum1, dv);
                        s2 = __fdiv_rn(sum2, dv); s3 = __fdiv_rn(sum3, dv);
                    }
                    *(float4*)&S_IC(b4, hq)[16] = make_float4(s0, s1, s2, s3);   // src slice
                }
            }
        }
        __syncwarp();                       // s_ic reads done before next quad
    }
}

extern "C" void kernel_launch(void* const* d_in, const int* in_sizes, int n_in,
                              void* d_out, int out_size) {
    const float* ui     = (const float*)d_in[0];
    const float* corpus = (const float*)d_in[1];
    const float* wp     = (const float*)d_in[2];
    const float* bp     = (const float*)d_in[3];
    const float* wk     = (const float*)d_in[4];
    const float* bk     = (const float*)d_in[5];
    float* out = (float*)d_out;
    int n_batch = in_sizes[0] / 16;

    const int smem_bytes = 57664;   // 48000 corpus + 9600 ic(+src/score in pads) + mbar
    static int attr_set = 0;
    if (!attr_set) {
        cudaFuncSetAttribute(attn_greedy_kernel,
                             cudaFuncAttributeMaxDynamicSharedMemorySize, smem_bytes);
        attr_set = 1;
    }
    // 96-thread blocks (3 warps), 57664B smem -> 4 blocks/SM (12 warps). 592 = 4 x 148.
    attn_greedy_kernel<<<592, 96, smem_bytes>>>(ui, corpus, wp, bp, wk, bk, out, n_batch);
}

// round 17
// speedup vs baseline: 1.2228x; 1.2228x over previous
#include <cuda_runtime.h>
#include <math.h>
#include <cstdint>

#define FULL_MASK 0xFFFFFFFFu
typedef unsigned long long ull;

__device__ __forceinline__ ull pk2(float lo, float hi) {
    ull r; asm("mov.b64 %0, {%1, %2};" : "=l"(r) : "f"(lo), "f"(hi)); return r;
}
__device__ __forceinline__ void fma2(ull& d, ull a, ull b) {
    asm("fma.rn.f32x2 %0, %1, %2, %0;" : "+l"(d) : "l"(a), "l"(b));
}
__device__ __forceinline__ void unpk(ull v, float& a, float& b) {
    asm("mov.b64 {%0, %1}, %2;" : "=f"(a), "=f"(b) : "l"(v));
}
__device__ __forceinline__ void mbar_wait(uint32_t mbar, int parity) {
    asm volatile(
        "{\n\t.reg .pred P;\n\t"
        "WAIT_%=:\n\t"
        "mbarrier.try_wait.parity.acquire.cta.shared::cta.b64 P, [%0], %1, 0x989680;\n\t"
        "@P bra.uni DONE_%=;\n\t"
        "bra.uni WAIT_%=;\n\t"
        "DONE_%=:\n\t}"
        :: "r"(mbar), "r"(parity) : "memory");
}

// bs=65536, S=10, D=100, H=16, 5 greedy steps.
// R17: DUO layout — 2 batches per warp; lane = (b2 = lane>>4, g = (lane>>3)&1,
// hh = lane&7). Lane owns 5 rows x 2 h-cols (h0 = 2*hh): one f32x2 pair per row.
// Corpus 8KB/warp via cp.async.bulk double-buffered in time -> 128-thread blocks,
// 39.3KB smem, 4 blocks/SM = 16 warps (R12's occupancy + R14's bulk L1 win).
// Score: one lane per (batch,row) (20 rows <= 32 lanes, no double-row tail).
//
// FROZEN numerics contract (rel_err 9.309e-8 since R4):
//   - every dot: single-accumulator sequential fmaf chain (ascending index), bias AFTER
//   - f32x2 = two INDEPENDENT h-column chains (lo/hi rounded separately)
//   - score: ONE lane per (batch,row), h=0..15 ascending scalar chain
//   - src = mean(ui): append-order sum; /2,/4 exact mul; /3,/5 via __fdiv_rn
//   - softmax skipped (monotone); first-index argmax via strict >
#define S_IC(b2, r)  (s_icA  + (((w << 1) + (b2)) * 10 + (r)) * 20)
#define S_SRC(b2)    (s_srcA + (((w << 1) + (b2)) << 4))
#define S_SCO(b2)    (s_scoA + ((w << 1) + (b2)) * 10)

__global__ __launch_bounds__(128, 4)
void attn_greedy_kernel(const float* __restrict__ g_ui,     // [bs,16]
                        const float* __restrict__ g_corp,   // [bs,10,100]
                        const float* __restrict__ g_wp,     // [100,16]
                        const float* __restrict__ g_bp,     // [16]
                        const float* __restrict__ g_wk,     // [16,16]
                        const float* __restrict__ g_bk,     // [16]
                        float* __restrict__ g_out,          // [bs,6,16]
                        int n_batch)
{
    extern __shared__ __align__(16) char smem_raw[];
    float* s_corpA = (float*)smem_raw;                    // [4][2000] corpus duo tiles
    float* s_icA   = (float*)(smem_raw + 32000);          // [4][2][10][20]
    float* s_srcA  = (float*)(smem_raw + 38400);          // [4][2][16]
    float* s_scoA  = (float*)(smem_raw + 38912);          // [4][2][10]
    ull*   s_mbarA = (ull*)(smem_raw + 39232);            // [4] mbarriers

    const int tid  = threadIdx.x;
    const int w    = tid >> 5;
    const int lane = tid & 31;
    const int b2   = lane >> 4;
    const int g    = (lane >> 3) & 1;
    const int hh   = lane & 7;
    const int h0   = hh << 1;

    float* scorp = s_corpA + w * 2000;
    const uint32_t mb = (uint32_t)__cvta_generic_to_shared(&s_mbarA[w]);
    if (lane == 0)
        asm volatile("mbarrier.init.shared.b64 [%0], %1;" :: "r"(mb), "r"(1) : "memory");
    __syncwarp();

    const int warp_id = (blockIdx.x << 2) + w;
    const int n_warps = gridDim.x << 2;
    const int n_duo   = (n_batch + 1) >> 1;

    float bp0, bp1, bk0, bk1;
    { float2 t = __ldg((const float2*)(g_bp + h0)); bp0 = t.x; bp1 = t.y; }
    { float2 t = __ldg((const float2*)(g_bk + h0)); bk0 = t.x; bk1 = t.y; }

    // ---- issue first corpus bulk (lane 0) ----
    int ph = 0;
    if (warp_id < n_duo && lane == 0) {
        asm volatile("mbarrier.arrive.expect_tx.shared.b64 _, [%0], %1;"
                     :: "r"(mb), "r"(8000) : "memory");
        #pragma unroll
        for (int jb = 0; jb < 2; jb++) {
            int bj = (warp_id << 1) + jb; if (bj >= n_batch) bj = n_batch - 1;
            uint32_t dst = (uint32_t)__cvta_generic_to_shared(scorp + jb * 1000);
            asm volatile("cp.async.bulk.shared::cta.global.mbarrier::complete_tx::bytes "
                         "[%0], [%1], %2, [%3];"
                         :: "r"(dst), "l"(g_corp + (size_t)bj * 1000), "r"(4000), "r"(mb)
                         : "memory");
        }
    }

    for (int du = warp_id; du < n_duo; du += n_warps) {
        const int  b     = (du << 1) + b2;
        const bool valid = (b < n_batch);
        const int  bl    = valid ? b : (n_batch - 1);

        // ---- ui (overlaps the bulk) ----
        float2 uv = __ldg((const float2*)(g_ui + (size_t)bl * 16 + h0));
        float sum0 = uv.x, sum1 = uv.y;
        if (g == 0) {
            *(float2*)&S_SRC(b2)[h0] = uv;
            if (valid) *(float2*)(g_out + (size_t)b * 96 + h0) = uv;
        }

        // ---- wait for this duo's corpus tile ----
        mbar_wait(mb, ph); ph ^= 1;

        // ---- projection: ic0[row][h] = seq-fma_{d=0..99} corp[row,d]*Wp[d,h], +bp ----
        ull acc[5];
        #pragma unroll
        for (int j = 0; j < 5; j++) acc[j] = 0ull;
        const float* crow = scorp + b2 * 1000 + (5 * g) * 100;   // broadcast LDS.128
        #pragma unroll 5
        for (int c = 0; c < 25; c++) {
            float4 x[5];
            #pragma unroll
            for (int j = 0; j < 5; j++)
                x[j] = *(const float4*)(crow + j * 100 + 4 * c);
            #pragma unroll
            for (int q = 0; q < 4; q++) {                        // d ascending
                ull wpp = __ldg((const ull*)(g_wp + (4*c + q) * 16 + h0));  // {Wp[d][h0],Wp[d][h0+1]}
                #pragma unroll
                for (int j = 0; j < 5; j++) {
                    float cd = (q == 0) ? x[j].x : (q == 1) ? x[j].y : (q == 2) ? x[j].z : x[j].w;
                    fma2(acc[j], pk2(cd, cd), wpp);
                }
            }
        }
        #pragma unroll
        for (int j = 0; j < 5; j++) {
            float a0, a1;
            unpk(acc[j], a0, a1);
            *(float2*)&S_IC(b2, 5*g + j)[h0] = make_float2(a0 + bp0, a1 + bp1);
        }
        __syncwarp();                       // all lanes done reading scorp

        // ---- issue NEXT duo's corpus bulk (lands under the step-loop) ----
        {
            const int ndu = du + n_warps;
            if (lane == 0 && ndu < n_duo) {
                asm volatile("mbarrier.arrive.expect_tx.shared.b64 _, [%0], %1;"
                             :: "r"(mb), "r"(8000) : "memory");
                #pragma unroll
                for (int jb = 0; jb < 2; jb++) {
                    int bj = (ndu << 1) + jb; if (bj >= n_batch) bj = n_batch - 1;
                    uint32_t dst = (uint32_t)__cvta_generic_to_shared(scorp + jb * 1000);
                    asm volatile("cp.async.bulk.shared::cta.global.mbarrier::complete_tx::bytes "
                                 "[%0], [%1], %2, [%3];"
                                 :: "r"(dst), "l"(g_corp + (size_t)bj * 1000), "r"(4000), "r"(mb)
                                 : "memory");
                }
            }
        }

        // ---- 5 greedy steps ----
        for (int t = 1; t <= 5; t++) {
            // nic[row][h] = seq-fma_{k=0..15} ic[row][k]*Wk[k][h], +bk
            ull np[5];
            #pragma unroll
            for (int j = 0; j < 5; j++) np[j] = 0ull;
            #pragma unroll
            for (int kc = 0; kc < 4; kc++) {
                float4 iv[5];
                #pragma unroll
                for (int j = 0; j < 5; j++)
                    iv[j] = *(const float4*)&S_IC(b2, 5*g + j)[4 * kc];
                #pragma unroll
                for (int q = 0; q < 4; q++) {                    // k = 4kc+q ascending
                    ull wkp = __ldg((const ull*)(g_wk + (4*kc + q) * 16 + h0));
                    #pragma unroll
                    for (int j = 0; j < 5; j++) {
                        float cd = (q == 0) ? iv[j].x : (q == 1) ? iv[j].y
                                 : (q == 2) ? iv[j].z : iv[j].w;
                        fma2(np[j], pk2(cd, cd), wkp);
                    }
                }
            }
            float nic[5][2];
            #pragma unroll
            for (int j = 0; j < 5; j++) {
                float a0, a1;
                unpk(np[j], a0, a1);
                nic[j][0] = a0 + bk0; nic[j][1] = a1 + bk1;
            }
            __syncwarp();                   // all k-reads of old ic done
            #pragma unroll
            for (int j = 0; j < 5; j++)
                *(float2*)&S_IC(b2, 5*g + j)[h0] = make_float2(nic[j][0], nic[j][1]);
            __syncwarp();                   // new ic visible

            // score[(sbt,row)] = seq-fma_{h=0..15} ic[row][h]*src[h]  (one lane per row)
            if (lane < 20) {
                const int sbt = (lane >= 10) ? 1 : 0;
                const int sr  = lane - 10 * sbt;
                const float* icr = S_IC(sbt, sr);
                const float* sv  = S_SRC(sbt);
                float a = 0.f;
                #pragma unroll
                for (int i = 0; i < 4; i++) {
                    float4 xx = *(const float4*)(icr + 4*i);
                    float4 yy = *(const float4*)(sv + 4*i);
                    a = fmaf(xx.x, yy.x, a); a = fmaf(xx.y, yy.y, a);     // h ascending
                    a = fmaf(xx.z, yy.z, a); a = fmaf(xx.w, yy.w, a);
                }
                S_SCO(sbt)[sr] = a;
            }
            __syncwarp();

            // first-index argmax (strict >, ascending row)
            float bv = -INFINITY; int idx = 0;
            #pragma unroll
            for (int j = 0; j < 10; j++) {
                float v = S_SCO(b2)[j];     // broadcast LDS
                if (v > bv) { bv = v; idx = j; }
            }

            // gather selected row: pack this lane's candidate pair, one 64-bit shfl
            const int jj = idx - 5 * g;     // 0..4 if this g owns the row
            ull cp = pk2(nic[0][0], nic[0][1]);
            #pragma unroll
            for (int j = 1; j < 5; j++)
                if (jj == j) cp = pk2(nic[j][0], nic[j][1]);
            const int srcl = (lane & 16) | ((idx >= 5) ? 8 : 0) | hh;
            ull itp = __shfl_sync(FULL_MASK, cp, srcl);
            float it0, it1;
            unpk(itp, it0, it1);

            sum0 += it0; sum1 += it1;       // append order
            if (g == 0) {
                if (valid)
                    *(float2*)(g_out + (size_t)b * 96 + (size_t)t * 16 + h0) =
                        make_float2(it0, it1);
                if (t < 5) {
                    float s0, s1;
                    if (t == 1)      { s0 = sum0 * 0.5f;  s1 = sum1 * 0.5f;  }
                    else if (t == 3) { s0 = sum0 * 0.25f; s1 = sum1 * 0.25f; }
                    else {
                        const float dv = (float)(t + 1);
                        s0 = __fdiv_rn(sum0, dv); s1 = __fdiv_rn(sum1, dv);
                    }
                    *(float2*)&S_SRC(b2)[h0] = make_float2(s0, s1);
                }
            }
        }
        __syncwarp();                       // smem reads done before next duo
    }
}

extern "C" void kernel_launch(void* const* d_in, const int* in_sizes, int n_in,
                              void* d_out, int out_size) {
    const float* ui     = (const float*)d_in[0];
    const float* corpus = (const float*)d_in[1];
    const float* wp     = (const float*)d_in[2];
    const float* bp     = (const float*)d_in[3];
    const float* wk     = (const float*)d_in[4];
    const float* bk     = (const float*)d_in[5];
    float* out = (float*)d_out;
    int n_batch = in_sizes[0] / 16;

    const int smem_bytes = 39264;   // 32000 corpus + 6400 ic + 512 src + 320 score + 32 mbar
    static int attr_set = 0;
    if (!attr_set) {
        cudaFuncSetAttribute(attn_greedy_kernel,
                             cudaFuncAttributeMaxDynamicSharedMemorySize, smem_bytes);
        attr_set = 1;
    }
    // 128-thread blocks (4 warps), 39.3KB smem -> 4 blocks/SM = 16 warps. 592 = 4 x 148.
    attn_greedy_kernel<<<592, 128, smem_bytes>>>(ui, corpus, wp, bp, wk, bk, out, n_batch);
}